// round 1
// baseline (speedup 1.0000x reference)
#include <cuda_runtime.h>
#include <cuda_bf16.h>
#include <cstdint>
#include <cstddef>

#define Bn 8
#define Tn 2048
#define Dn 128

// ---- scratch (static device globals; no allocations) ----
__device__ __nv_bfloat16 g_zbf[Bn * Tn * Dn];   // 4 MB
__device__ float        g_z2[Bn * Tn];          // 64 KB
__device__ double       g_part[Bn * 16 * 16];   // 2048 partials

// ============================================================
// Kernel 1: bf16 cast of z + per-row squared norms
// grid = B*T blocks, 128 threads (one row each)
// ============================================================
__global__ void prep_kernel(const float* __restrict__ z) {
    int row = blockIdx.x;              // b*T + t
    int tid = threadIdx.x;             // 0..127 = d
    int idx = row * Dn + tid;
    float v = z[idx];
    g_zbf[idx] = __float2bfloat16(v);
    float ss = v * v;
    #pragma unroll
    for (int o = 16; o; o >>= 1) ss += __shfl_xor_sync(0xffffffffu, ss, o);
    __shared__ float s[4];
    if ((tid & 31) == 0) s[tid >> 5] = ss;
    __syncthreads();
    if (tid == 0) g_z2[row] = s[0] + s[1] + s[2] + s[3];
}

// ============================================================
// Kernel 2: fused Gram(MMA) + w + weighted reduction
// grid = (16, 16, 8) = (jt, it, b); 256 threads (8 warps, 4x2)
// smem: zi[128][136] bf16, zj[128][136] bf16, z2i[128], z2j[128]
// ============================================================
#define SM_WSTRIDE 68   // 136 bf16 = 68 words per row (pad kills bank conflicts)
#define SMEM_BYTES (2 * 128 * SM_WSTRIDE * 4 + 2 * 128 * 4)

extern __shared__ unsigned char smem_raw[];

__global__ void __launch_bounds__(256, 2)
main_kernel(const float* __restrict__ gt, const float* __restrict__ sigma) {
    uint32_t* zi  = (uint32_t*)smem_raw;
    uint32_t* zj  = zi + 128 * SM_WSTRIDE;
    float*    z2i = (float*)(zj + 128 * SM_WSTRIDE);
    float*    z2j = z2i + 128;

    const int jt = blockIdx.x, it = blockIdx.y, b = blockIdx.z;
    const int i0 = it * 128, j0 = jt * 128;
    const int tid = threadIdx.x;

    // ---- load z tiles (bf16, 16B vectors) ----
    const uint4* zsrc = (const uint4*)g_zbf;     // one row = 16 uint4
    #pragma unroll
    for (int p = 0; p < 8; p++) {
        int idx = tid + p * 256;                 // 0..2047
        int r = idx >> 4, c = idx & 15;
        uint4 vi = zsrc[(size_t)(b * Tn + i0 + r) * 16 + c];
        *((uint4*)(zi + r * SM_WSTRIDE + c * 4)) = vi;
        uint4 vj = zsrc[(size_t)(b * Tn + j0 + r) * 16 + c];
        *((uint4*)(zj + r * SM_WSTRIDE + c * 4)) = vj;
    }
    if (tid < 128) z2i[tid] = g_z2[b * Tn + i0 + tid];
    else           z2j[tid - 128] = g_z2[b * Tn + j0 + (tid - 128)];
    __syncthreads();

    // ---- Gram 128x128 via mma.sync m16n8k16 bf16 ----
    const int warp = tid >> 5, lane = tid & 31;
    const int wm = warp & 3, wn = warp >> 1 & 0 ? 0 : (warp >> 2);  // 4 x 2
    const int rowBase = wm * 32, colBase = wn * 64;
    const int gr = lane >> 2, q = lane & 3;

    float acc[2][8][4];
    #pragma unroll
    for (int fm = 0; fm < 2; fm++)
        #pragma unroll
        for (int fn = 0; fn < 8; fn++)
            #pragma unroll
            for (int v = 0; v < 4; v++) acc[fm][fn][v] = 0.f;

    #pragma unroll
    for (int ks = 0; ks < 8; ks++) {
        const int kw = ks * 8 + q;               // word offset within row
        uint32_t a[2][4];
        #pragma unroll
        for (int fm = 0; fm < 2; fm++) {
            int r = rowBase + fm * 16 + gr;
            a[fm][0] = zi[r * SM_WSTRIDE + kw];
            a[fm][1] = zi[(r + 8) * SM_WSTRIDE + kw];
            a[fm][2] = zi[r * SM_WSTRIDE + kw + 4];
            a[fm][3] = zi[(r + 8) * SM_WSTRIDE + kw + 4];
        }
        #pragma unroll
        for (int fn = 0; fn < 8; fn++) {
            int n = colBase + fn * 8 + gr;
            uint32_t b0 = zj[n * SM_WSTRIDE + kw];
            uint32_t b1 = zj[n * SM_WSTRIDE + kw + 4];
            #pragma unroll
            for (int fm = 0; fm < 2; fm++) {
                asm volatile(
                    "mma.sync.aligned.m16n8k16.row.col.f32.bf16.bf16.f32 "
                    "{%0,%1,%2,%3}, {%4,%5,%6,%7}, {%8,%9}, {%0,%1,%2,%3};"
                    : "+f"(acc[fm][fn][0]), "+f"(acc[fm][fn][1]),
                      "+f"(acc[fm][fn][2]), "+f"(acc[fm][fn][3])
                    : "r"(a[fm][0]), "r"(a[fm][1]), "r"(a[fm][2]), "r"(a[fm][3]),
                      "r"(b0), "r"(b1));
            }
        }
    }

    // ---- epilogue: stream gt, compute w, weighted accumulate ----
    float s0 = sigma[0], s1 = sigma[1];
    float c0 = 1.0f / (2.0f * s0 * s0), c1 = 1.0f / (2.0f * s1 * s1);
    const float4* gt4 = (const float4*)gt;       // {g(j,0),g(j,1),g(j+1,0),g(j+1,1)}
    float sum = 0.f;

    #pragma unroll
    for (int fm = 0; fm < 2; fm++) {
        const int ri = rowBase + fm * 16 + gr;
        const float z2a = z2i[ri];
        const float z2b = z2i[ri + 8];
        const size_t base0 = (size_t)(b * Tn + i0 + ri) * Tn + j0;
        const size_t base1 = base0 + (size_t)8 * Tn;
        #pragma unroll
        for (int fn = 0; fn < 8; fn++) {
            const int jj = colBase + fn * 8 + 2 * q;   // local col (even)
            const float zj0 = z2j[jj], zj1 = z2j[jj + 1];
            const float4 gA = gt4[(base0 + jj) >> 1];
            const float4 gB = gt4[(base1 + jj) >> 1];
            const float w00 = __expf(-(gA.x * gA.x * c0 + gA.y * gA.y * c1));
            const float w01 = __expf(-(gA.z * gA.z * c0 + gA.w * gA.w * c1));
            const float w10 = __expf(-(gB.x * gB.x * c0 + gB.y * gB.y * c1));
            const float w11 = __expf(-(gB.z * gB.z * c0 + gB.w * gB.w * c1));
            sum += w00 * (z2a + zj0 - 2.f * acc[fm][fn][0]);
            sum += w01 * (z2a + zj1 - 2.f * acc[fm][fn][1]);
            sum += w10 * (z2b + zj0 - 2.f * acc[fm][fn][2]);
            sum += w11 * (z2b + zj1 - 2.f * acc[fm][fn][3]);
        }
    }

    // ---- block reduce -> per-CTA partial ----
    #pragma unroll
    for (int o = 16; o; o >>= 1) sum += __shfl_xor_sync(0xffffffffu, sum, o);
    __shared__ float wsum[8];
    if (lane == 0) wsum[warp] = sum;
    __syncthreads();
    if (tid == 0) {
        float t = 0.f;
        #pragma unroll
        for (int w = 0; w < 8; w++) t += wsum[w];
        g_part[(b * 16 + it) * 16 + jt] = (double)t;
    }
}

// ============================================================
// Kernel 3: deterministic final reduce
// ============================================================
__global__ void reduce_kernel(float* __restrict__ out) {
    int tid = threadIdx.x;
    double s = 0.0;
    for (int i = tid; i < Bn * 16 * 16; i += 256) s += g_part[i];
    __shared__ double sh[256];
    sh[tid] = s;
    __syncthreads();
    for (int o = 128; o; o >>= 1) {
        if (tid < o) sh[tid] += sh[tid + o];
        __syncthreads();
    }
    if (tid == 0)
        out[0] = (float)(sh[0] / ((double)Bn * (double)Tn * (double)Tn));
}

// ============================================================
extern "C" void kernel_launch(void* const* d_in, const int* in_sizes, int n_in,
                              void* d_out, int out_size) {
    const float *z = nullptr, *gt = nullptr, *sg = nullptr;
    for (int i = 0; i < n_in; i++) {
        if (in_sizes[i] == Bn * Tn * Dn)      z  = (const float*)d_in[i];
        else if (in_sizes[i] == 2)            sg = (const float*)d_in[i];
        else                                  gt = (const float*)d_in[i];
    }

    cudaFuncSetAttribute(main_kernel,
                         cudaFuncAttributeMaxDynamicSharedMemorySize, SMEM_BYTES);

    prep_kernel<<<Bn * Tn, 128>>>(z);
    dim3 grid(16, 16, Bn);
    main_kernel<<<grid, 256, SMEM_BYTES>>>(gt, sg);
    reduce_kernel<<<1, 256>>>((float*)d_out);
}

// round 2
// speedup vs baseline: 1.1401x; 1.1401x over previous
#include <cuda_runtime.h>
#include <cuda_bf16.h>
#include <cstdint>
#include <cstddef>

#define Bn 8
#define Tn 2048
#define Dn 128

// ---- scratch (static device globals; no allocations) ----
__device__ __nv_bfloat16 g_zbf[Bn * Tn * Dn];   // 4 MB
__device__ float        g_z2[Bn * Tn];          // 64 KB
__device__ double       g_part[Bn * 16 * 16];   // 2048 partials

// ============================================================
// Kernel 1: bf16 cast of z + per-row squared norms
// warp-per-row, float4 loads. grid = B*T/8 blocks x 256 thr.
// ============================================================
__global__ void __launch_bounds__(256) prep_kernel(const float* __restrict__ z) {
    const int warp = threadIdx.x >> 5, lane = threadIdx.x & 31;
    const int row = blockIdx.x * 8 + warp;             // b*T + t
    const float4 v = ((const float4*)(z + (size_t)row * Dn))[lane];

    __nv_bfloat162 p0 = __floats2bfloat162_rn(v.x, v.y);
    __nv_bfloat162 p1 = __floats2bfloat162_rn(v.z, v.w);
    uint2 o;
    o.x = *reinterpret_cast<uint32_t*>(&p0);
    o.y = *reinterpret_cast<uint32_t*>(&p1);
    ((uint2*)g_zbf)[(size_t)row * 32 + lane] = o;

    float ss = v.x * v.x + v.y * v.y + v.z * v.z + v.w * v.w;
    #pragma unroll
    for (int off = 16; off; off >>= 1) ss += __shfl_xor_sync(0xffffffffu, ss, off);
    if (lane == 0) g_z2[row] = ss;
}

// ============================================================
// Kernel 2: fused Gram(MMA) + w + weighted reduction
// grid = (16, 16, 8) = (jt, it, b); 256 threads (8 warps, 4x2)
// smem: zi[128][136] bf16, zj[128][136] bf16, z2i[128], z2j[128]
// ============================================================
#define SM_WSTRIDE 68   // 136 bf16 = 68 words per row (pad kills bank conflicts)
#define SMEM_BYTES (2 * 128 * SM_WSTRIDE * 4 + 2 * 128 * 4)

extern __shared__ unsigned char smem_raw[];

__global__ void __launch_bounds__(256, 2)
main_kernel(const float* __restrict__ gt, const float* __restrict__ sigma) {
    uint32_t* zi  = (uint32_t*)smem_raw;
    uint32_t* zj  = zi + 128 * SM_WSTRIDE;
    float*    z2i = (float*)(zj + 128 * SM_WSTRIDE);
    float*    z2j = z2i + 128;

    const int jt = blockIdx.x, it = blockIdx.y, b = blockIdx.z;
    const int i0 = it * 128, j0 = jt * 128;
    const int tid = threadIdx.x;

    // ---- L2 prefetch of this CTA's 128KB gt tile (overlaps MMA phase) ----
    // tile row (b, i0+r): 128 j * 2 K * 4 B = 1024 B = 8 x 128B lines
    {
        const char* gbase = (const char*)gt;
        #pragma unroll
        for (int p = 0; p < 4; p++) {
            int idx = tid + p * 256;                 // 0..1023
            int r = idx >> 3, c = idx & 7;
            const char* addr = gbase +
                ((size_t)(b * Tn + i0 + r) * Tn + j0) * 8 + (size_t)c * 128;
            asm volatile("prefetch.global.L2 [%0];" :: "l"(addr));
        }
    }

    // ---- load z tiles (bf16, 16B vectors) ----
    const uint4* zsrc = (const uint4*)g_zbf;     // one row = 16 uint4
    #pragma unroll
    for (int p = 0; p < 8; p++) {
        int idx = tid + p * 256;                 // 0..2047
        int r = idx >> 4, c = idx & 15;
        uint4 vi = zsrc[(size_t)(b * Tn + i0 + r) * 16 + c];
        *((uint4*)(zi + r * SM_WSTRIDE + c * 4)) = vi;
        uint4 vj = zsrc[(size_t)(b * Tn + j0 + r) * 16 + c];
        *((uint4*)(zj + r * SM_WSTRIDE + c * 4)) = vj;
    }
    if (tid < 128) z2i[tid] = g_z2[b * Tn + i0 + tid];
    else           z2j[tid - 128] = g_z2[b * Tn + j0 + (tid - 128)];
    __syncthreads();

    // ---- Gram 128x128 via mma.sync m16n8k16 bf16 ----
    const int warp = tid >> 5, lane = tid & 31;
    const int wm = warp & 3, wn = warp >> 2;     // 4 x 2 warp grid
    const int rowBase = wm * 32, colBase = wn * 64;
    const int gr = lane >> 2, q = lane & 3;

    float acc[2][8][4];
    #pragma unroll
    for (int fm = 0; fm < 2; fm++)
        #pragma unroll
        for (int fn = 0; fn < 8; fn++)
            #pragma unroll
            for (int v = 0; v < 4; v++) acc[fm][fn][v] = 0.f;

    #pragma unroll
    for (int ks = 0; ks < 8; ks++) {
        const int kw = ks * 8 + q;               // word offset within row
        uint32_t a[2][4];
        #pragma unroll
        for (int fm = 0; fm < 2; fm++) {
            int r = rowBase + fm * 16 + gr;
            a[fm][0] = zi[r * SM_WSTRIDE + kw];
            a[fm][1] = zi[(r + 8) * SM_WSTRIDE + kw];
            a[fm][2] = zi[r * SM_WSTRIDE + kw + 4];
            a[fm][3] = zi[(r + 8) * SM_WSTRIDE + kw + 4];
        }
        #pragma unroll
        for (int fn = 0; fn < 8; fn++) {
            int n = colBase + fn * 8 + gr;
            uint32_t b0 = zj[n * SM_WSTRIDE + kw];
            uint32_t b1 = zj[n * SM_WSTRIDE + kw + 4];
            #pragma unroll
            for (int fm = 0; fm < 2; fm++) {
                asm volatile(
                    "mma.sync.aligned.m16n8k16.row.col.f32.bf16.bf16.f32 "
                    "{%0,%1,%2,%3}, {%4,%5,%6,%7}, {%8,%9}, {%0,%1,%2,%3};"
                    : "+f"(acc[fm][fn][0]), "+f"(acc[fm][fn][1]),
                      "+f"(acc[fm][fn][2]), "+f"(acc[fm][fn][3])
                    : "r"(a[fm][0]), "r"(a[fm][1]), "r"(a[fm][2]), "r"(a[fm][3]),
                      "r"(b0), "r"(b1));
            }
        }
    }

    // ---- epilogue: stream gt (now L2-hot), compute w, weighted accumulate ----
    float s0 = sigma[0], s1 = sigma[1];
    float c0 = 1.0f / (2.0f * s0 * s0), c1 = 1.0f / (2.0f * s1 * s1);
    const float4* gt4 = (const float4*)gt;       // {g(j,0),g(j,1),g(j+1,0),g(j+1,1)}
    float sum = 0.f;

    #pragma unroll
    for (int fm = 0; fm < 2; fm++) {
        const int ri = rowBase + fm * 16 + gr;
        const float z2a = z2i[ri];
        const float z2b = z2i[ri + 8];
        const size_t base0 = (size_t)(b * Tn + i0 + ri) * Tn + j0;
        const size_t base1 = base0 + (size_t)8 * Tn;
        #pragma unroll
        for (int fn = 0; fn < 8; fn++) {
            const int jj = colBase + fn * 8 + 2 * q;   // local col (even)
            const float zj0 = z2j[jj], zj1 = z2j[jj + 1];
            const float4 gA = gt4[(base0 + jj) >> 1];
            const float4 gB = gt4[(base1 + jj) >> 1];
            const float w00 = __expf(-(gA.x * gA.x * c0 + gA.y * gA.y * c1));
            const float w01 = __expf(-(gA.z * gA.z * c0 + gA.w * gA.w * c1));
            const float w10 = __expf(-(gB.x * gB.x * c0 + gB.y * gB.y * c1));
            const float w11 = __expf(-(gB.z * gB.z * c0 + gB.w * gB.w * c1));
            sum += w00 * (z2a + zj0 - 2.f * acc[fm][fn][0]);
            sum += w01 * (z2a + zj1 - 2.f * acc[fm][fn][1]);
            sum += w10 * (z2b + zj0 - 2.f * acc[fm][fn][2]);
            sum += w11 * (z2b + zj1 - 2.f * acc[fm][fn][3]);
        }
    }

    // ---- block reduce -> per-CTA partial ----
    #pragma unroll
    for (int o = 16; o; o >>= 1) sum += __shfl_xor_sync(0xffffffffu, sum, o);
    __shared__ float wsum[8];
    if (lane == 0) wsum[warp] = sum;
    __syncthreads();
    if (tid == 0) {
        float t = 0.f;
        #pragma unroll
        for (int w = 0; w < 8; w++) t += wsum[w];
        g_part[(b * 16 + it) * 16 + jt] = (double)t;
    }
}

// ============================================================
// Kernel 3: deterministic final reduce
// ============================================================
__global__ void reduce_kernel(float* __restrict__ out) {
    int tid = threadIdx.x;
    double s = 0.0;
    for (int i = tid; i < Bn * 16 * 16; i += 256) s += g_part[i];
    __shared__ double sh[256];
    sh[tid] = s;
    __syncthreads();
    for (int o = 128; o; o >>= 1) {
        if (tid < o) sh[tid] += sh[tid + o];
        __syncthreads();
    }
    if (tid == 0)
        out[0] = (float)(sh[0] / ((double)Bn * (double)Tn * (double)Tn));
}

// ============================================================
extern "C" void kernel_launch(void* const* d_in, const int* in_sizes, int n_in,
                              void* d_out, int out_size) {
    const float *z = nullptr, *gt = nullptr, *sg = nullptr;
    for (int i = 0; i < n_in; i++) {
        if (in_sizes[i] == Bn * Tn * Dn)      z  = (const float*)d_in[i];
        else if (in_sizes[i] == 2)            sg = (const float*)d_in[i];
        else                                  gt = (const float*)d_in[i];
    }

    cudaFuncSetAttribute(main_kernel,
                         cudaFuncAttributeMaxDynamicSharedMemorySize, SMEM_BYTES);

    prep_kernel<<<Bn * Tn / 8, 256>>>(z);
    dim3 grid(16, 16, Bn);
    main_kernel<<<grid, 256, SMEM_BYTES>>>(gt, sg);
    reduce_kernel<<<1, 256>>>((float*)d_out);
}